// round 16
// baseline (speedup 1.0000x reference)
#include <cuda_runtime.h>
#include <math.h>

#define BATCH 32
#define WG 640
#define HG 480
#define WH (WG*HG)          /* 307200 */
#define IMG_H 480
#define IMG_W 640

__device__ float g_max;
__device__ float g_neg_inf = -INFINITY;

__device__ __forceinline__ float frcp_fast(float x){
    float r; asm("rcp.approx.f32 %0, %1;" : "=f"(r) : "f"(x)); return r;
}

// Fused per-batch matrices:
//   q = d * ([x,y,1] @ M) + c,  M = K^-1 @ T33 @ K (3x3),  c = T[3,0:3] @ K (3)
// uv = (q0, q1) / (q2 + 1e-4)
__device__ __forceinline__ void compute_mats(
    const float* __restrict__ K, const float* __restrict__ T,
    float* __restrict__ M, float* __restrict__ c)
{
    float a=K[0],b=K[1],cc=K[2],d=K[3],e=K[4],f=K[5],g=K[6],h=K[7],i=K[8];
    float det = a*(e*i - f*h) - b*(d*i - f*g) + cc*(d*h - e*g);
    float id = 1.0f/det;
    float Ki[9];
    Ki[0]=(e*i-f*h)*id; Ki[1]=(cc*h-b*i)*id; Ki[2]=(b*f-cc*e)*id;
    Ki[3]=(f*g-d*i)*id; Ki[4]=(a*i-cc*g)*id; Ki[5]=(cc*d-a*f)*id;
    Ki[6]=(d*h-e*g)*id; Ki[7]=(b*g-a*h)*id; Ki[8]=(a*e-b*d)*id;

    float G[9];   // T33 @ K
    #pragma unroll
    for (int r=0;r<3;r++)
        #pragma unroll
        for (int cl=0;cl<3;cl++)
            G[r*3+cl] = T[r*4+0]*K[cl] + T[r*4+1]*K[3+cl] + T[r*4+2]*K[6+cl];
    #pragma unroll
    for (int r=0;r<3;r++)
        #pragma unroll
        for (int cl=0;cl<3;cl++)
            M[r*3+cl] = Ki[r*3+0]*G[cl] + Ki[r*3+1]*G[3+cl] + Ki[r*3+2]*G[6+cl];
    #pragma unroll
    for (int cl=0;cl<3;cl++)
        c[cl] = T[12]*K[cl] + T[13]*K[3+cl] + T[14]*K[6+cl];
}

// Pass 1: global max of all uv components. 8 px/thread, incremental s-update
// (y fixed per thread, x increments by 1: s(x+1) = s(x) + M_row0).
__global__ __launch_bounds__(256) void k_pass1(
    const float* __restrict__ depth, const float* __restrict__ trans,
    const float* __restrict__ Kp)
{
    __shared__ float sM[9], sc[3];
    int b = blockIdx.y;
    if (threadIdx.x == 0) {
        float Kl[9], Tl[16];
        #pragma unroll
        for (int i=0;i<9;i++)  Kl[i] = __ldg(Kp + i);
        #pragma unroll
        for (int i=0;i<16;i++) Tl[i] = __ldg(trans + b*16 + i);
        compute_mats(Kl, Tl, sM, sc);
    }
    __syncthreads();
    float M0=sM[0], M1=sM[1], M2=sM[2];
    float c0=sc[0], c1=sc[1], c2=sc[2];

    int t = blockIdx.x*256 + threadIdx.x;
    int pix = t*8;
    int w = pix/HG;
    int h = pix - w*HG;        // 8 | 480, so h..h+7 stay in one row
    float y = (float)w;
    float hf = (float)h;

    float s0 = fmaf(hf, M0, fmaf(y, sM[3], sM[6]));
    float s1 = fmaf(hf, M1, fmaf(y, sM[4], sM[7]));
    float s2 = fmaf(hf, M2, fmaf(y, sM[5], sM[8]));

    const float4* dp = reinterpret_cast<const float4*>(depth + (size_t)b*WH + pix);
    float4 a4 = dp[0], b4 = dp[1];
    float dd[8] = {a4.x,a4.y,a4.z,a4.w, b4.x,b4.y,b4.z,b4.w};

    float m = -INFINITY;
    #pragma unroll
    for (int k=0;k<8;k++){
        float q0 = fmaf(dd[k], s0, c0);
        float q1 = fmaf(dd[k], s1, c1);
        float q2 = fmaf(dd[k], s2, c2);
        float inv = frcp_fast(q2 + 1e-4f);
        m = fmaxf(m, fmaxf(q0*inv, q1*inv));
        s0 += M0; s1 += M1; s2 += M2;
    }
    #pragma unroll
    for (int o=16;o>0;o>>=1) m = fmaxf(m, __shfl_xor_sync(0xffffffffu, m, o));

    __shared__ float sm[8];
    if ((threadIdx.x & 31)==0) sm[threadIdx.x>>5] = m;
    __syncthreads();
    if (threadIdx.x==0){
        float bm = sm[0];
        #pragma unroll
        for (int i=1;i<8;i++) bm = fmaxf(bm, sm[i]);
        if (bm >= 0.0f) atomicMax((int*)&g_max, __float_as_int(bm));
        else            atomicMin((unsigned int*)&g_max, __float_as_uint(bm));
    }
}

// Pass 2: normalize + bilinear grid_sample (zeros padding). 4 px/thread.
// Incremental s-update + per-thread all-inside fast path (unpredicated loads).
__global__ __launch_bounds__(256) void k_pass2(
    const float* __restrict__ depth, const float* __restrict__ trans,
    const float* __restrict__ Kp, const float* __restrict__ img,
    float* __restrict__ out)
{
    __shared__ float sM[9], sc[3];
    int b = blockIdx.y;
    if (threadIdx.x == 0) {
        float Kl[9], Tl[16];
        #pragma unroll
        for (int i=0;i<9;i++)  Kl[i] = __ldg(Kp + i);
        #pragma unroll
        for (int i=0;i<16;i++) Tl[i] = __ldg(trans + b*16 + i);
        compute_mats(Kl, Tl, sM, sc);
    }
    __syncthreads();
    float M0=sM[0], M1=sM[1], M2=sM[2];
    float c0=sc[0], c1=sc[1], c2=sc[2];

    int t = blockIdx.x*256 + threadIdx.x;
    int pix = t*4;
    int w = pix/HG;
    int h = pix - w*HG;        // 4 | 480, row-local
    float y = (float)w;
    float hf = (float)h;

    float Gm = g_max;
    float ig = frcp_fast(Gm);
    float fx = (float)IMG_W * ig;
    float fy = (float)IMG_H * ig;

    float s0 = fmaf(hf, M0, fmaf(y, sM[3], sM[6]));
    float s1 = fmaf(hf, M1, fmaf(y, sM[4], sM[7]));
    float s2 = fmaf(hf, M2, fmaf(y, sM[5], sM[8]));

    float4 d4 = *reinterpret_cast<const float4*>(depth + (size_t)b*WH + pix);
    float dd[4] = {d4.x, d4.y, d4.z, d4.w};

    // Compute all 4 sample coords first.
    float xs[4], ys[4];
    bool inside = true;
    #pragma unroll
    for (int k=0;k<4;k++){
        float q0 = fmaf(dd[k], s0, c0);
        float q1 = fmaf(dd[k], s1, c1);
        float q2 = fmaf(dd[k], s2, c2);
        float inv = frcp_fast(q2 + 1e-4f);
        xs[k] = fmaf(q0*inv, fx, -0.5f);
        ys[k] = fmaf(q1*inv, fy, -0.5f);
        s0 += M0; s1 += M1; s2 += M2;
        // full 4-tap validity <=> xs in [0, W-1) and ys in [0, H-1)
        inside = inside && (xs[k] >= 0.0f) && (xs[k] < (float)(IMG_W-1))
                        && (ys[k] >= 0.0f) && (ys[k] < (float)(IMG_H-1));
    }

    const float* imgb = img + (size_t)b*3*WH;
    float res[3][4];

    if (inside) {
        // Fast path: every tap valid -> no predicates, plain loads.
        #pragma unroll
        for (int k=0;k<4;k++){
            int x0 = __float2int_rd(xs[k]);
            int y0 = __float2int_rd(ys[k]);
            float wx = xs[k] - __int2float_rn(x0);
            float wy = ys[k] - __int2float_rn(y0);
            float omx = 1.0f - wx, omy = 1.0f - wy;
            float w00 = omx*omy, w01 = wx*omy, w10 = omx*wy, w11 = wx*wy;
            int i00 = y0*IMG_W + x0;
            #pragma unroll
            for (int ch=0;ch<3;ch++){
                const float* p = imgb + (size_t)ch*WH + i00;
                float s  = __ldg(p) * w00;
                s = fmaf(__ldg(p + 1),         w01, s);
                s = fmaf(__ldg(p + IMG_W),     w10, s);
                s = fmaf(__ldg(p + IMG_W + 1), w11, s);
                res[ch][k] = s;
            }
        }
    } else {
        // Slow path: per-tap predicated (identical semantics to prior rounds).
        #pragma unroll
        for (int k=0;k<4;k++){
            int x0 = __float2int_rd(xs[k]);
            int y0 = __float2int_rd(ys[k]);
            float wx = xs[k] - __int2float_rn(x0);
            float wy = ys[k] - __int2float_rn(y0);
            float omx = 1.0f - wx, omy = 1.0f - wy;

            bool vx0 = ((unsigned)x0       < (unsigned)IMG_W);
            bool vx1 = ((unsigned)(x0 + 1) < (unsigned)IMG_W);
            bool vy0 = ((unsigned)y0       < (unsigned)IMG_H);
            bool vy1 = ((unsigned)(y0 + 1) < (unsigned)IMG_H);
            bool b00 = vx0 && vy0, b01 = vx1 && vy0;
            bool b10 = vx0 && vy1, b11 = vx1 && vy1;

            float w00 = omx*omy, w01 = wx*omy, w10 = omx*wy, w11 = wx*wy;
            int i00 = y0*IMG_W + x0;
            #pragma unroll
            for (int ch=0;ch<3;ch++){
                const float* p = imgb + (size_t)ch*WH + i00;
                float s = 0.0f;
                if (b00) s = fmaf(__ldg(p),           w00, s);
                if (b01) s = fmaf(__ldg(p + 1),       w01, s);
                if (b10) s = fmaf(__ldg(p + IMG_W),   w10, s);
                if (b11) s = fmaf(__ldg(p + IMG_W+1), w11, s);
                res[ch][k] = s;
            }
        }
    }

    size_t ob = (size_t)b*3*WH + (size_t)w*HG + (size_t)h;
    #pragma unroll
    for (int ch=0;ch<3;ch++){
        float4 o = make_float4(res[ch][0], res[ch][1], res[ch][2], res[ch][3]);
        *reinterpret_cast<float4*>(out + ob + (size_t)ch*WH) = o;
    }
}

extern "C" void kernel_launch(void* const* d_in, const int* in_sizes, int n_in,
                              void* d_out, int out_size)
{
    const float *depth=nullptr, *trans=nullptr, *img=nullptr, *K=nullptr;
    for (int i=0;i<n_in;i++){
        switch (in_sizes[i]) {
            case BATCH*WH:    depth = (const float*)d_in[i]; break;   // 9830400
            case BATCH*16:    trans = (const float*)d_in[i]; break;   // 512
            case BATCH*3*WH:  img   = (const float*)d_in[i]; break;   // 29491200
            case 9:           K     = (const float*)d_in[i]; break;
        }
    }
    if (!depth && n_in > 0) depth = (const float*)d_in[0];
    if (!trans && n_in > 1) trans = (const float*)d_in[1];
    if (!img   && n_in > 2) img   = (const float*)d_in[2];
    if (!K     && n_in > 3) K     = (const float*)d_in[3];

    float* out = (float*)d_out;

    // Reset g_max to -inf with a tiny d2d memcpy node.
    void *pmax = nullptr, *pninf = nullptr;
    cudaGetSymbolAddress(&pmax,  g_max);
    cudaGetSymbolAddress(&pninf, g_neg_inf);
    cudaMemcpyAsync(pmax, pninf, sizeof(float), cudaMemcpyDeviceToDevice);

    dim3 g1(WH/8/256, BATCH);   // (150, 32)
    dim3 g2(WH/4/256, BATCH);   // (300, 32)
    k_pass1<<<g1,256>>>(depth, trans, K);
    k_pass2<<<g2,256>>>(depth, trans, K, img, out);
}